// round 9
// baseline (speedup 1.0000x reference)
#include <cuda_runtime.h>
#include <cstdint>
#include <cstddef>

// Xonv2D: out[b,o,h,w] = sum_{c,kh,kw} x[b,c,h+kh-1,w+kw-1] * W[h,w,o,c,kh,kw] + bias[h,w,o]
// B=4, CIN=COUT=16, K=3, H=W=128. Weights = 151MB streamed once -> HBM-bound.
// Round 9: x pre-transposed once to padded xT[c][h+1][w+1][b] (zero halo baked in);
// per-chunk x tile loaded by 48x96B bulk-TMA rows into a row-padded smem layout
// (19 float4 per c -> both weight LDS and x LDS at the 2-phase crossbar floor).
// Weight TMA ring-3 unchanged; epilogue = round-7 smem transpose (proven).

static constexpr int Hc = 128, Wc = 128;
static constexpr int GROUPS = 4096;                      // 4-pixel groups
static constexpr int RING = 3;
static constexpr int FLOATS_PER_PX = 16 * 16 * 9;        // 2304
static constexpr int CHUNK_FLOATS  = 4 * FLOATS_PER_PX;  // 9216
static constexpr int CHUNK_BYTES   = CHUNK_FLOATS * 4;   // 36864
static constexpr int CSTR          = 19;                 // float4 words per c in x tile (18 + 1 pad)
static constexpr int XTILE_BYTES   = 16 * CSTR * 16;     // 4864
static constexpr int XT_BYTES      = 48 * 96;            // 4608 actually transferred
static constexpr int SMEM_X_OFF    = RING * CHUNK_BYTES;            // 110592
static constexpr int SMEM_MBAR_OFF = SMEM_X_OFF + XTILE_BYTES;      // 115456
static constexpr int SMEM_TOTAL    = SMEM_MBAR_OFF + RING * 8 + 8;  // 115488 (<=116224 for 2 CTAs/SM)
static constexpr int GRID          = 304;
static constexpr int NT            = 256;

// Padded transposed x: [c][h'][w'][b], h' = h+1 in 0..129, w' = w+1 in 0..131 (132 for align).
static constexpr int XT_HP = 130, XT_WP = 132;
__device__ float g_xT[16 * XT_HP * XT_WP * 4];

__global__ void __launch_bounds__(256) transpose_kernel(const float* __restrict__ x) {
    const int i = blockIdx.x * 256 + threadIdx.x;     // linear over (c, hp, wp)
    if (i >= 16 * XT_HP * XT_WP) return;
    const int wp = i % XT_WP;
    const int hp = (i / XT_WP) % XT_HP;
    const int c  = i / (XT_WP * XT_HP);
    const int h = hp - 1, w = wp - 1;
    float4 v = make_float4(0.f, 0.f, 0.f, 0.f);
    if ((unsigned)h < 128u && (unsigned)w < 128u) {
        const float* p = x + ((size_t)c * Hc + h) * Wc + w;   // b=0
        v.x = __ldg(p);
        v.y = __ldg(p + 16 * Hc * Wc);
        v.z = __ldg(p + 32 * Hc * Wc);
        v.w = __ldg(p + 48 * Hc * Wc);
    }
    reinterpret_cast<float4*>(g_xT)[i] = v;
}

__device__ __forceinline__ uint32_t smem_u32(const void* p) {
    return (uint32_t)__cvta_generic_to_shared(p);
}
__device__ __forceinline__ void mbar_init(uint32_t a, uint32_t count) {
    asm volatile("mbarrier.init.shared.b64 [%0], %1;" :: "r"(a), "r"(count) : "memory");
}
__device__ __forceinline__ void mbar_expect_tx(uint32_t a, uint32_t bytes) {
    asm volatile("mbarrier.arrive.expect_tx.shared.b64 _, [%0], %1;" :: "r"(a), "r"(bytes) : "memory");
}
__device__ __forceinline__ void tma_bulk_g2s(uint32_t dst, const void* src, uint32_t bytes, uint32_t mbar) {
    asm volatile("cp.async.bulk.shared::cta.global.mbarrier::complete_tx::bytes [%0], [%1], %2, [%3];"
                 :: "r"(dst), "l"(src), "r"(bytes), "r"(mbar) : "memory");
}
__device__ __forceinline__ void mbar_wait(uint32_t a, uint32_t parity) {
    uint32_t done;
    asm volatile(
        "{\n\t.reg .pred p;\n\t"
        "mbarrier.try_wait.parity.acquire.cta.shared::cta.b64 p, [%1], %2;\n\t"
        "selp.b32 %0, 1, 0, p;\n\t}"
        : "=r"(done) : "r"(a), "r"(parity) : "memory");
    while (!done) {
        asm volatile(
            "{\n\t.reg .pred p;\n\t"
            "mbarrier.try_wait.parity.acquire.cta.shared::cta.b64 p, [%1], %2, 0x989680;\n\t"
            "selp.b32 %0, 1, 0, p;\n\t}"
            : "=r"(done) : "r"(a), "r"(parity) : "memory");
    }
}

__global__ void __launch_bounds__(NT, 2)
xonv2d_kernel(const float* __restrict__ wts,
              const float* __restrict__ bias,
              float* __restrict__ out)
{
    extern __shared__ char smem[];
    float*  swt = reinterpret_cast<float*>(smem);
    float*  sx  = reinterpret_cast<float*>(smem + SMEM_X_OFF);
    float4* sx4 = reinterpret_cast<float4*>(smem + SMEM_X_OFF);
    const uint32_t mb  = smem_u32(smem + SMEM_MBAR_OFF);   // 3 weight mbars
    const uint32_t mbx = mb + RING * 8;                    // x-tile mbar

    const int t   = threadIdx.x;
    const int bid = blockIdx.x;

    if (t == 0) {
        #pragma unroll
        for (int s = 0; s < RING; s++) mbar_init(mb + s * 8, 1);
        mbar_init(mbx, 1);
    }
    __syncthreads();

    // Prologue: weight TMA for chunks bid (slot0), bid+GRID (slot1).
    if (t == 0) {
        mbar_expect_tx(mb + 0, CHUNK_BYTES);
        tma_bulk_g2s(smem_u32(swt), wts + (size_t)bid * CHUNK_FLOATS, CHUNK_BYTES, mb + 0);
        if (bid + GRID < GROUPS) {
            mbar_expect_tx(mb + 8, CHUNK_BYTES);
            tma_bulk_g2s(smem_u32(swt + CHUNK_FLOATS),
                         wts + (size_t)(bid + GRID) * CHUNK_FLOATS, CHUNK_BYTES, mb + 8);
        }
    }

    // Lane mapping: o0l=bit0, ch=bits1-3 (cin pair), o0h=bit4; warp: o0m=bit5, px=bits6-7.
    const int o0  = (t & 1) + 2 * ((t >> 4) & 1) + 4 * ((t >> 5) & 1);
    const int ch  = (t >> 1) & 7;
    const int px  = (t >> 6) & 3;
    const int wbase_f2 = px * (FLOATS_PER_PX / 2) + o0 * 72 + ch * 9;
    const int xb0 = (2 * ch) * CSTR + px;
    const int xb1 = xb0 + CSTR;

    // bias prefetch for first chunk (t<64: o = t&15, 4 pixels of group bid).
    float bs0 = 0.f, bs1 = 0.f, bs2 = 0.f, bs3 = 0.f;
    if (t < 64) {
        const float* bp = bias + (size_t)bid * 64 + (t & 15);
        bs0 = __ldg(bp); bs1 = __ldg(bp + 16); bs2 = __ldg(bp + 32); bs3 = __ldg(bp + 48);
    }

    const float* xT = g_xT;

    for (int j = 0, gi = bid; gi < GROUPS; j++, gi += GRID) {
        const int slot   = j % RING;
        const int parity = (j / RING) & 1;

        __syncthreads();   // S1: prev epilogue reads done -> sx writable, slot j-1 free

        const int pix0 = gi * 4;
        const int h0   = pix0 >> 7;
        const int w0   = pix0 & 127;

        // x-tile TMA: 48 rows of 96B (c=0..15, r=0..2), issued by warp 0.
        if (t < 32) {
            if (t == 0) mbar_expect_tx(mbx, XT_BYTES);
            __syncwarp();
            {
                const int c = t / 3, r = t - c * 3;
                tma_bulk_g2s(smem_u32(sx) + (uint32_t)(c * CSTR + r * 6) * 16,
                             xT + ((size_t)(c * XT_HP + h0 + r) * XT_WP + w0) * 4,
                             96, mbx);
            }
            if (t < 16) {
                const int idx = t + 32;
                const int c = idx / 3, r = idx - c * 3;
                tma_bulk_g2s(smem_u32(sx) + (uint32_t)(c * CSTR + r * 6) * 16,
                             xT + ((size_t)(c * XT_HP + h0 + r) * XT_WP + w0) * 4,
                             96, mbx);
            }
        }
        // Weight TMA for chunk j+2 (issued from warp 1, parallel with warp 0).
        if (t == 32) {
            int gn = gi + (RING - 1) * GRID;
            if (gn < GROUPS) {
                int sn = (j + RING - 1) % RING;
                mbar_expect_tx(mb + sn * 8, CHUNK_BYTES);
                tma_bulk_g2s(smem_u32(swt + sn * CHUNK_FLOATS),
                             wts + (size_t)gn * CHUNK_FLOATS, CHUNK_BYTES, mb + sn * 8);
            }
        }

        // bias prefetch for next chunk (hidden behind mbar waits).
        float bn0 = 0.f, bn1 = 0.f, bn2 = 0.f, bn3 = 0.f;
        if (t < 64 && gi + GRID < GROUPS) {
            const float* bp = bias + (size_t)(gi + GRID) * 64 + (t & 15);
            bn0 = __ldg(bp); bn1 = __ldg(bp + 16); bn2 = __ldg(bp + 32); bn3 = __ldg(bp + 48);
        }

        mbar_wait(mb + slot * 8, parity);  // weights ready (DRAM-paced, usually last)
        mbar_wait(mbx, j & 1);             // x tile ready (L2, usually already done)

        const float2* wp = reinterpret_cast<const float2*>(swt + slot * CHUNK_FLOATS) + wbase_f2;

        float a00 = 0.f, a01 = 0.f, a02 = 0.f, a03 = 0.f;
        float a10 = 0.f, a11 = 0.f, a12 = 0.f, a13 = 0.f;

        #pragma unroll
        for (int k = 0; k < 9; k++) {
            const float2 w0v = wp[k];          // cout o0
            const float2 w1v = wp[k + 576];    // cout o0+8
            #pragma unroll
            for (int e = 0; e < 2; e++) {
                const int f   = 2 * k + e;     // 0..17
                const int cc  = f / 9;
                const int tap = f % 9;
                const int r   = tap / 3;
                const int s   = tap % 3;
                const float4 xv = sx4[(cc ? xb1 : xb0) + r * 6 + s];
                const float wa = e ? w0v.y : w0v.x;
                const float wb = e ? w1v.y : w1v.x;
                a00 += wa * xv.x;  a01 += wa * xv.y;  a02 += wa * xv.z;  a03 += wa * xv.w;
                a10 += wb * xv.x;  a11 += wb * xv.y;  a12 += wb * xv.z;  a13 += wb * xv.w;
            }
        }

        // Reduce over ch (lane bits 1-3): 3 butterflies.
        #pragma unroll
        for (int m = 2; m <= 8; m <<= 1) {
            a00 += __shfl_xor_sync(0xffffffffu, a00, m);
            a01 += __shfl_xor_sync(0xffffffffu, a01, m);
            a02 += __shfl_xor_sync(0xffffffffu, a02, m);
            a03 += __shfl_xor_sync(0xffffffffu, a03, m);
            a10 += __shfl_xor_sync(0xffffffffu, a10, m);
            a11 += __shfl_xor_sync(0xffffffffu, a11, m);
            a12 += __shfl_xor_sync(0xffffffffu, a12, m);
            a13 += __shfl_xor_sync(0xffffffffu, a13, m);
        }

        __syncthreads();   // S3: all sx reads done -> sout (overlaid on sx) writable

        if (ch == 0) {
            const int o1 = o0 + 8;
            sx[(0 * 16 + o0) * 4 + px] = a00;
            sx[(1 * 16 + o0) * 4 + px] = a01;
            sx[(2 * 16 + o0) * 4 + px] = a02;
            sx[(3 * 16 + o0) * 4 + px] = a03;
            sx[(0 * 16 + o1) * 4 + px] = a10;
            sx[(1 * 16 + o1) * 4 + px] = a11;
            sx[(2 * 16 + o1) * 4 + px] = a12;
            sx[(3 * 16 + o1) * 4 + px] = a13;
        }
        __syncthreads();   // S4: sout ready

        // Coalesced write: thread t<64 -> (b = t>>4, o = t&15), float4 over 4 pixels.
        if (t < 64) {
            float4 v = sx4[t];
            v.x += bs0; v.y += bs1; v.z += bs2; v.w += bs3;
            *reinterpret_cast<float4*>(out + (size_t)t * (Hc * Wc) + pix0) = v;
            bs0 = bn0; bs1 = bn1; bs2 = bn2; bs3 = bn3;
        }
    }
}

extern "C" void kernel_launch(void* const* d_in, const int* in_sizes, int n_in,
                              void* d_out, int out_size) {
    const float* x    = (const float*)d_in[0];
    const float* wts  = (const float*)d_in[1];
    const float* bias = (const float*)d_in[2];
    float* out        = (float*)d_out;

    cudaFuncSetAttribute(xonv2d_kernel, cudaFuncAttributeMaxDynamicSharedMemorySize, SMEM_TOTAL);

    const int ttot = 16 * XT_HP * XT_WP;
    transpose_kernel<<<(ttot + 255) / 256, 256>>>(x);
    xonv2d_kernel<<<GRID, NT, SMEM_TOTAL>>>(wts, bias, out);
}

// round 10
// speedup vs baseline: 1.4269x; 1.4269x over previous
#include <cuda_runtime.h>
#include <cuda_fp16.h>
#include <cstdint>
#include <cstddef>

// Xonv2D: out[b,o,h,w] = sum_{c,kh,kw} x[b,c,h+kh-1,w+kw-1] * W[h,w,o,c,kh,kw] + bias[h,w,o]
// B=4, CIN=COUT=16, K=3, H=W=128. Weights = 151MB streamed once -> HBM-bound.
// Round 10: 3 CTAs/SM (24 warps). Weight ring shrunk to 2 slots, x halo tile
// stored fp16 (fp32 accumulation) -> smem 76048B fits 3 CTAs. Otherwise the
// proven R7 structure: conflict-free LDS mappings, x reg-prefetch one chunk
// ahead, bias reg-prefetch, smem-transpose coalesced epilogue.

static constexpr int Hc = 128, Wc = 128;
static constexpr int GROUPS = 4096;                      // 4-pixel groups
static constexpr int FLOATS_PER_PX = 16 * 16 * 9;        // 2304
static constexpr int CHUNK_FLOATS  = 4 * FLOATS_PER_PX;  // 9216
static constexpr int CHUNK_BYTES   = CHUNK_FLOATS * 4;   // 36864
static constexpr int XTILE         = 1152;               // halfs (16c*3r*6w*4b)
static constexpr int SMEM_X_OFF    = 2 * CHUNK_BYTES;            // 73728
static constexpr int SMEM_MBAR_OFF = SMEM_X_OFF + XTILE * 2;     // 76032
static constexpr int SMEM_TOTAL    = SMEM_MBAR_OFF + 16;         // 76048 (x3 = 228144 <= 233472)
static constexpr int GRID          = 456;                // 3 CTAs/SM * 152 SMs
static constexpr int NT            = 256;

__device__ __forceinline__ uint32_t smem_u32(const void* p) {
    return (uint32_t)__cvta_generic_to_shared(p);
}
__device__ __forceinline__ void mbar_init(uint32_t a, uint32_t count) {
    asm volatile("mbarrier.init.shared.b64 [%0], %1;" :: "r"(a), "r"(count) : "memory");
}
__device__ __forceinline__ void mbar_expect_tx(uint32_t a, uint32_t bytes) {
    asm volatile("mbarrier.arrive.expect_tx.shared.b64 _, [%0], %1;" :: "r"(a), "r"(bytes) : "memory");
}
__device__ __forceinline__ void tma_bulk_g2s(uint32_t dst, const void* src, uint32_t bytes, uint32_t mbar) {
    asm volatile("cp.async.bulk.shared::cta.global.mbarrier::complete_tx::bytes [%0], [%1], %2, [%3];"
                 :: "r"(dst), "l"(src), "r"(bytes), "r"(mbar) : "memory");
}
__device__ __forceinline__ void mbar_wait(uint32_t a, uint32_t parity) {
    uint32_t done;
    asm volatile(
        "{\n\t.reg .pred p;\n\t"
        "mbarrier.try_wait.parity.acquire.cta.shared::cta.b64 p, [%1], %2;\n\t"
        "selp.b32 %0, 1, 0, p;\n\t}"
        : "=r"(done) : "r"(a), "r"(parity) : "memory");
    while (!done) {
        asm volatile(
            "{\n\t.reg .pred p;\n\t"
            "mbarrier.try_wait.parity.acquire.cta.shared::cta.b64 p, [%1], %2, 0x989680;\n\t"
            "selp.b32 %0, 1, 0, p;\n\t}"
            : "=r"(done) : "r"(a), "r"(parity) : "memory");
    }
}

__global__ void __launch_bounds__(NT, 3)
xonv2d_kernel(const float* __restrict__ x,
              const float* __restrict__ wts,
              const float* __restrict__ bias,
              float* __restrict__ out)
{
    extern __shared__ char smem[];
    float*   swt  = reinterpret_cast<float*>(smem);
    __half*  sxh  = reinterpret_cast<__half*>(smem + SMEM_X_OFF);
    float*   sof  = reinterpret_cast<float*>(smem + SMEM_X_OFF);   // epilogue overlay
    float4*  sof4 = reinterpret_cast<float4*>(smem + SMEM_X_OFF);
    const uint2* sxu2 = reinterpret_cast<const uint2*>(smem + SMEM_X_OFF);
    const uint32_t mb = smem_u32(smem + SMEM_MBAR_OFF);

    const int t   = threadIdx.x;
    const int bid = blockIdx.x;

    if (t == 0) { mbar_init(mb, 1); mbar_init(mb + 8, 1); }
    __syncthreads();

    // Prologue: weight TMA for chunks bid (slot0), bid+GRID (slot1).
    if (t == 0) {
        mbar_expect_tx(mb, CHUNK_BYTES);
        tma_bulk_g2s(smem_u32(swt), wts + (size_t)bid * CHUNK_FLOATS, CHUNK_BYTES, mb);
        mbar_expect_tx(mb + 8, CHUNK_BYTES);
        tma_bulk_g2s(smem_u32(swt + CHUNK_FLOATS),
                     wts + (size_t)(bid + GRID) * CHUNK_FLOATS, CHUNK_BYTES, mb + 8);
    }

    // Lane mapping: o0l=bit0, ch=bits1-3 (cin pair), o0h=bit4; warp: o0m=bit5, px=bits6-7.
    const int o0  = (t & 1) + 2 * ((t >> 4) & 1) + 4 * ((t >> 5) & 1);
    const int ch  = (t >> 1) & 7;
    const int px  = (t >> 6) & 3;
    const int xsw = (ch >> 1) & 3;
    const int wbase_f2 = px * (FLOATS_PER_PX / 2) + o0 * 72 + ch * 9;
    const int xb0 = (2 * ch) * 18 + px;
    const int xb1 = xb0 + 18;

    // Precomputed x-fill constants (loop-invariant).
    int goff[5], sidx[5], pk[5];
    #pragma unroll
    for (int it = 0; it < 5; it++) {
        const int i = t + it * NT;
        if (i < XTILE) {
            const int wi = i % 6;
            const int r  = (i / 6) % 3;
            const int c  = (i / 18) % 16;
            const int b  = i / 288;
            goff[it] = ((b * 16 + c) * Hc + (r - 1)) * Wc + (wi - 1);
            sidx[it] = ((c * 18 + r * 6 + wi) ^ ((c >> 2) & 3)) * 4 + b;
            pk[it]   = r | (wi << 4);
        }
    }

    // x prefetch for first chunk.
    float xr[5];
    {
        const int p0 = bid * 4;
        const int h0 = p0 >> 7, w0 = p0 & 127;
        #pragma unroll
        for (int it = 0; it < 5; it++) {
            const int i = t + it * NT;
            if (i < XTILE) {
                const int hh = h0 + (pk[it] & 15) - 1;
                const int ww = w0 + (pk[it] >> 4) - 1;
                xr[it] = ((unsigned)hh < 128u && (unsigned)ww < 128u)
                         ? __ldg(x + goff[it] + p0) : 0.0f;
            }
        }
    }
    // bias prefetch for first chunk.
    float bs0 = 0.f, bs1 = 0.f, bs2 = 0.f, bs3 = 0.f;
    if (t < 64) {
        const float* bp = bias + (size_t)bid * 64 + (t & 15);
        bs0 = __ldg(bp); bs1 = __ldg(bp + 16); bs2 = __ldg(bp + 32); bs3 = __ldg(bp + 48);
    }

    for (int j = 0, gi = bid; gi < GROUPS; j++, gi += GRID) {
        const int slot   = j & 1;
        const int parity = (j >> 1) & 1;

        __syncthreads();   // S1: prev epilogue reads done -> x tile writable

        // Store prefetched x (fp16) into the tile.
        #pragma unroll
        for (int it = 0; it < 5; it++) {
            const int i = t + it * NT;
            if (i < XTILE) sxh[sidx[it]] = __float2half_rn(xr[it]);
        }
        __syncthreads();   // S2: x tile ready

        // Prefetch x + bias for next chunk (hidden behind mbar_wait + compute).
        float bn0 = 0.f, bn1 = 0.f, bn2 = 0.f, bn3 = 0.f;
        {
            const int gn1 = gi + GRID;
            if (gn1 < GROUPS) {
                const int p1 = gn1 * 4;
                const int h0 = p1 >> 7, w0 = p1 & 127;
                #pragma unroll
                for (int it = 0; it < 5; it++) {
                    const int i = t + it * NT;
                    if (i < XTILE) {
                        const int hh = h0 + (pk[it] & 15) - 1;
                        const int ww = w0 + (pk[it] >> 4) - 1;
                        xr[it] = ((unsigned)hh < 128u && (unsigned)ww < 128u)
                                 ? __ldg(x + goff[it] + p1) : 0.0f;
                    }
                }
                if (t < 64) {
                    const float* bp = bias + (size_t)gn1 * 64 + (t & 15);
                    bn0 = __ldg(bp); bn1 = __ldg(bp + 16);
                    bn2 = __ldg(bp + 32); bn3 = __ldg(bp + 48);
                }
            }
        }

        mbar_wait(mb + slot * 8, parity);  // weights for chunk gi ready

        const float2* wp = reinterpret_cast<const float2*>(swt + slot * CHUNK_FLOATS) + wbase_f2;

        float a00 = 0.f, a01 = 0.f, a02 = 0.f, a03 = 0.f;
        float a10 = 0.f, a11 = 0.f, a12 = 0.f, a13 = 0.f;

        #pragma unroll
        for (int k = 0; k < 9; k++) {
            const float2 w0v = wp[k];          // cout o0
            const float2 w1v = wp[k + 576];    // cout o0+8
            #pragma unroll
            for (int e = 0; e < 2; e++) {
                const int f   = 2 * k + e;     // 0..17
                const int cc  = f / 9;
                const int tap = f % 9;
                const int r   = tap / 3;
                const int s   = tap % 3;
                const int W   = ((cc ? xb1 : xb0) + r * 6 + s) ^ xsw;
                union { uint2 u; __half2 h[2]; } raw;
                raw.u = sxu2[W];
                const float2 lo = __half22float2(raw.h[0]);
                const float2 hi = __half22float2(raw.h[1]);
                const float wa = e ? w0v.y : w0v.x;
                const float wb = e ? w1v.y : w1v.x;
                a00 += wa * lo.x;  a01 += wa * lo.y;  a02 += wa * hi.x;  a03 += wa * hi.y;
                a10 += wb * lo.x;  a11 += wb * lo.y;  a12 += wb * hi.x;  a13 += wb * hi.y;
            }
        }

        // Reduce over ch (lane bits 1-3): 3 butterflies.
        #pragma unroll
        for (int m = 2; m <= 8; m <<= 1) {
            a00 += __shfl_xor_sync(0xffffffffu, a00, m);
            a01 += __shfl_xor_sync(0xffffffffu, a01, m);
            a02 += __shfl_xor_sync(0xffffffffu, a02, m);
            a03 += __shfl_xor_sync(0xffffffffu, a03, m);
            a10 += __shfl_xor_sync(0xffffffffu, a10, m);
            a11 += __shfl_xor_sync(0xffffffffu, a11, m);
            a12 += __shfl_xor_sync(0xffffffffu, a12, m);
            a13 += __shfl_xor_sync(0xffffffffu, a13, m);
        }

        __syncthreads();   // S3: all x-tile + weight-slot reads done

        // Weight TMA for chunk j+2 into this (now free) slot.
        if (t == 0) {
            const int gn = gi + 2 * GRID;
            if (gn < GROUPS) {
                mbar_expect_tx(mb + slot * 8, CHUNK_BYTES);
                tma_bulk_g2s(smem_u32(swt + slot * CHUNK_FLOATS),
                             wts + (size_t)gn * CHUNK_FLOATS, CHUNK_BYTES, mb + slot * 8);
            }
        }

        // Stage outputs (fp32, overlaid on the x tile): sout[(b*16+o)*4 + px].
        if (ch == 0) {
            const int o1 = o0 + 8;
            sof[(0 * 16 + o0) * 4 + px] = a00;
            sof[(1 * 16 + o0) * 4 + px] = a01;
            sof[(2 * 16 + o0) * 4 + px] = a02;
            sof[(3 * 16 + o0) * 4 + px] = a03;
            sof[(0 * 16 + o1) * 4 + px] = a10;
            sof[(1 * 16 + o1) * 4 + px] = a11;
            sof[(2 * 16 + o1) * 4 + px] = a12;
            sof[(3 * 16 + o1) * 4 + px] = a13;
        }
        __syncthreads();   // S4: sout ready

        // Coalesced write: thread t<64 -> (b = t>>4, o = t&15), float4 over 4 pixels.
        if (t < 64) {
            float4 v = sof4[t];
            v.x += bs0; v.y += bs1; v.z += bs2; v.w += bs3;
            *reinterpret_cast<float4*>(out + (size_t)t * (Hc * Wc) + gi * 4) = v;
            bs0 = bn0; bs1 = bn1; bs2 = bn2; bs3 = bn3;
        }
    }
}

extern "C" void kernel_launch(void* const* d_in, const int* in_sizes, int n_in,
                              void* d_out, int out_size) {
    const float* x    = (const float*)d_in[0];
    const float* wts  = (const float*)d_in[1];
    const float* bias = (const float*)d_in[2];
    float* out        = (float*)d_out;

    cudaFuncSetAttribute(xonv2d_kernel, cudaFuncAttributeMaxDynamicSharedMemorySize, SMEM_TOTAL);
    xonv2d_kernel<<<GRID, NT, SMEM_TOTAL>>>(x, wts, bias, out);
}

// round 11
// speedup vs baseline: 1.4281x; 1.0009x over previous
#include <cuda_runtime.h>
#include <cuda_fp16.h>
#include <cstdint>
#include <cstddef>

// Xonv2D: out[b,o,h,w] = sum_{c,kh,kw} x[b,c,h+kh-1,w+kw-1] * W[h,w,o,c,kh,kw] + bias[h,w,o]
// B=4, CIN=COUT=16, K=3, H=W=128. Weights = 151MB streamed once -> HBM-bound.
// Round 11: 3 CTAs/SM (24 warps), ONLY 2 barriers/iter (separate sout buffer),
// weight chunk split into two 18.4KB TMA halves with per-warp mbar waits
// (px 0-1 warps wait half0, px 2-3 warps wait half1). x tile fp16, fp32 accum.

static constexpr int Hc = 128, Wc = 128;
static constexpr int GROUPS = 4096;                      // 4-pixel groups
static constexpr int FLOATS_PER_PX = 16 * 16 * 9;        // 2304
static constexpr int CHUNK_FLOATS  = 4 * FLOATS_PER_PX;  // 9216
static constexpr int CHUNK_BYTES   = CHUNK_FLOATS * 4;   // 36864
static constexpr int HALF_BYTES    = CHUNK_BYTES / 2;    // 18432 (px 0-1 | px 2-3)
static constexpr int XTILE         = 1152;               // halfs (16c*3r*6w*4b)
static constexpr int SMEM_X_OFF    = 2 * CHUNK_BYTES;            // 73728
static constexpr int SMEM_OUT_OFF  = SMEM_X_OFF + XTILE * 2;     // 76032
static constexpr int SMEM_MBAR_OFF = SMEM_OUT_OFF + 256 * 4;     // 77056
static constexpr int SMEM_TOTAL    = SMEM_MBAR_OFF + 32;         // 77088 (x3 = 231264 <= 233472)
static constexpr int GRID          = 456;                // 3 CTAs/SM * 152 SMs
static constexpr int NT            = 256;

__device__ __forceinline__ uint32_t smem_u32(const void* p) {
    return (uint32_t)__cvta_generic_to_shared(p);
}
__device__ __forceinline__ void mbar_init(uint32_t a, uint32_t count) {
    asm volatile("mbarrier.init.shared.b64 [%0], %1;" :: "r"(a), "r"(count) : "memory");
}
__device__ __forceinline__ void mbar_expect_tx(uint32_t a, uint32_t bytes) {
    asm volatile("mbarrier.arrive.expect_tx.shared.b64 _, [%0], %1;" :: "r"(a), "r"(bytes) : "memory");
}
__device__ __forceinline__ void tma_bulk_g2s(uint32_t dst, const void* src, uint32_t bytes, uint32_t mbar) {
    asm volatile("cp.async.bulk.shared::cta.global.mbarrier::complete_tx::bytes [%0], [%1], %2, [%3];"
                 :: "r"(dst), "l"(src), "r"(bytes), "r"(mbar) : "memory");
}
__device__ __forceinline__ void mbar_wait(uint32_t a, uint32_t parity) {
    uint32_t done;
    asm volatile(
        "{\n\t.reg .pred p;\n\t"
        "mbarrier.try_wait.parity.acquire.cta.shared::cta.b64 p, [%1], %2;\n\t"
        "selp.b32 %0, 1, 0, p;\n\t}"
        : "=r"(done) : "r"(a), "r"(parity) : "memory");
    while (!done) {
        asm volatile(
            "{\n\t.reg .pred p;\n\t"
            "mbarrier.try_wait.parity.acquire.cta.shared::cta.b64 p, [%1], %2, 0x989680;\n\t"
            "selp.b32 %0, 1, 0, p;\n\t}"
            : "=r"(done) : "r"(a), "r"(parity) : "memory");
    }
}

__global__ void __launch_bounds__(NT, 3)
xonv2d_kernel(const float* __restrict__ x,
              const float* __restrict__ wts,
              const float* __restrict__ bias,
              float* __restrict__ out)
{
    extern __shared__ char smem[];
    float*   swt  = reinterpret_cast<float*>(smem);
    __half*  sxh  = reinterpret_cast<__half*>(smem + SMEM_X_OFF);
    const uint2* sxu2 = reinterpret_cast<const uint2*>(smem + SMEM_X_OFF);
    float*   sof  = reinterpret_cast<float*>(smem + SMEM_OUT_OFF);
    float4*  sof4 = reinterpret_cast<float4*>(smem + SMEM_OUT_OFF);
    const uint32_t mb = smem_u32(smem + SMEM_MBAR_OFF);   // [slot][half] : slot*16 + half*8

    const int t   = threadIdx.x;
    const int bid = blockIdx.x;

    if (t == 0) {
        mbar_init(mb,      1); mbar_init(mb + 8,  1);
        mbar_init(mb + 16, 1); mbar_init(mb + 24, 1);
    }
    __syncthreads();

    // Prologue: weight TMA halves for chunks bid (slot0) and bid+GRID (slot1).
    if (t == 0) {
        const float* s0 = wts + (size_t)bid * CHUNK_FLOATS;
        const float* s1 = wts + (size_t)(bid + GRID) * CHUNK_FLOATS;
        mbar_expect_tx(mb + 0, HALF_BYTES);
        tma_bulk_g2s(smem_u32(swt), s0, HALF_BYTES, mb + 0);
        mbar_expect_tx(mb + 8, HALF_BYTES);
        tma_bulk_g2s(smem_u32(swt) + HALF_BYTES, s0 + CHUNK_FLOATS / 2, HALF_BYTES, mb + 8);
        mbar_expect_tx(mb + 16, HALF_BYTES);
        tma_bulk_g2s(smem_u32(swt) + CHUNK_BYTES, s1, HALF_BYTES, mb + 16);
        mbar_expect_tx(mb + 24, HALF_BYTES);
        tma_bulk_g2s(smem_u32(swt) + CHUNK_BYTES + HALF_BYTES, s1 + CHUNK_FLOATS / 2, HALF_BYTES, mb + 24);
    }

    // Lane mapping: o0l=bit0, ch=bits1-3 (cin pair), o0h=bit4; warp: o0m=bit5, px=bits6-7.
    const int o0  = (t & 1) + 2 * ((t >> 4) & 1) + 4 * ((t >> 5) & 1);
    const int ch  = (t >> 1) & 7;
    const int px  = (t >> 6) & 3;
    const int half = px >> 1;                 // which weight half this warp reads
    const int xsw = (ch >> 1) & 3;
    const int wbase_f2 = px * (FLOATS_PER_PX / 2) + o0 * 72 + ch * 9;
    const int xb0 = (2 * ch) * 18 + px;
    const int xb1 = xb0 + 18;

    // Precomputed x-fill constants (loop-invariant).
    int goff[5], sidx[5], pk[5];
    #pragma unroll
    for (int it = 0; it < 5; it++) {
        const int i = t + it * NT;
        if (i < XTILE) {
            const int wi = i % 6;
            const int r  = (i / 6) % 3;
            const int c  = (i / 18) % 16;
            const int b  = i / 288;
            goff[it] = ((b * 16 + c) * Hc + (r - 1)) * Wc + (wi - 1);
            sidx[it] = ((c * 18 + r * 6 + wi) ^ ((c >> 2) & 3)) * 4 + b;
            pk[it]   = r | (wi << 4);
        }
    }

    // x prefetch for first chunk.
    float xr[5];
    {
        const int p0 = bid * 4;
        const int h0 = p0 >> 7, w0 = p0 & 127;
        #pragma unroll
        for (int it = 0; it < 5; it++) {
            const int i = t + it * NT;
            if (i < XTILE) {
                const int hh = h0 + (pk[it] & 15) - 1;
                const int ww = w0 + (pk[it] >> 4) - 1;
                xr[it] = ((unsigned)hh < 128u && (unsigned)ww < 128u)
                         ? __ldg(x + goff[it] + p0) : 0.0f;
            }
        }
    }
    // bias prefetch for first chunk.
    float bs0 = 0.f, bs1 = 0.f, bs2 = 0.f, bs3 = 0.f;
    if (t < 64) {
        const float* bp = bias + (size_t)bid * 64 + (t & 15);
        bs0 = __ldg(bp); bs1 = __ldg(bp + 16); bs2 = __ldg(bp + 32); bs3 = __ldg(bp + 48);
    }

    for (int j = 0, gi = bid; gi < GROUPS; j++, gi += GRID) {
        const int slot   = j & 1;
        const int parity = (j >> 1) & 1;

        // STS x (fp16). Safe: S4(j-1) guaranteed all compute(j-1) reads done.
        #pragma unroll
        for (int it = 0; it < 5; it++) {
            const int i = t + it * NT;
            if (i < XTILE) sxh[sidx[it]] = __float2half_rn(xr[it]);
        }

        // Prefetch x + bias for next chunk (LDGs issued before the barrier).
        float bn0 = 0.f, bn1 = 0.f, bn2 = 0.f, bn3 = 0.f;
        {
            const int gn1 = gi + GRID;
            if (gn1 < GROUPS) {
                const int p1 = gn1 * 4;
                const int h0 = p1 >> 7, w0 = p1 & 127;
                #pragma unroll
                for (int it = 0; it < 5; it++) {
                    const int i = t + it * NT;
                    if (i < XTILE) {
                        const int hh = h0 + (pk[it] & 15) - 1;
                        const int ww = w0 + (pk[it] >> 4) - 1;
                        xr[it] = ((unsigned)hh < 128u && (unsigned)ww < 128u)
                                 ? __ldg(x + goff[it] + p1) : 0.0f;
                    }
                }
                if (t < 64) {
                    const float* bp = bias + (size_t)gn1 * 64 + (t & 15);
                    bn0 = __ldg(bp); bn1 = __ldg(bp + 16);
                    bn2 = __ldg(bp + 32); bn3 = __ldg(bp + 48);
                }
            }
        }

        __syncthreads();   // S2: x tile ready (and all STG(j-1) sout reads done)

        // Per-warp wait on only the weight half this warp reads.
        mbar_wait(mb + slot * 16 + half * 8, parity);

        const float2* wp = reinterpret_cast<const float2*>(swt + slot * CHUNK_FLOATS) + wbase_f2;

        float a00 = 0.f, a01 = 0.f, a02 = 0.f, a03 = 0.f;
        float a10 = 0.f, a11 = 0.f, a12 = 0.f, a13 = 0.f;

        #pragma unroll
        for (int k = 0; k < 9; k++) {
            const float2 w0v = wp[k];          // cout o0
            const float2 w1v = wp[k + 576];    // cout o0+8
            #pragma unroll
            for (int e = 0; e < 2; e++) {
                const int f   = 2 * k + e;     // 0..17
                const int cc  = f / 9;
                const int tap = f % 9;
                const int r   = tap / 3;
                const int s   = tap % 3;
                const int W   = ((cc ? xb1 : xb0) + r * 6 + s) ^ xsw;
                union { uint2 u; __half2 h[2]; } raw;
                raw.u = sxu2[W];
                const float2 lo = __half22float2(raw.h[0]);
                const float2 hi = __half22float2(raw.h[1]);
                const float wa = e ? w0v.y : w0v.x;
                const float wb = e ? w1v.y : w1v.x;
                a00 += wa * lo.x;  a01 += wa * lo.y;  a02 += wa * hi.x;  a03 += wa * hi.y;
                a10 += wb * lo.x;  a11 += wb * lo.y;  a12 += wb * hi.x;  a13 += wb * hi.y;
            }
        }

        // Reduce over ch (lane bits 1-3): 3 butterflies.
        #pragma unroll
        for (int m = 2; m <= 8; m <<= 1) {
            a00 += __shfl_xor_sync(0xffffffffu, a00, m);
            a01 += __shfl_xor_sync(0xffffffffu, a01, m);
            a02 += __shfl_xor_sync(0xffffffffu, a02, m);
            a03 += __shfl_xor_sync(0xffffffffu, a03, m);
            a10 += __shfl_xor_sync(0xffffffffu, a10, m);
            a11 += __shfl_xor_sync(0xffffffffu, a11, m);
            a12 += __shfl_xor_sync(0xffffffffu, a12, m);
            a13 += __shfl_xor_sync(0xffffffffu, a13, m);
        }

        // Stage outputs into the dedicated sout buffer.
        if (ch == 0) {
            const int o1 = o0 + 8;
            sof[(0 * 16 + o0) * 4 + px] = a00;
            sof[(1 * 16 + o0) * 4 + px] = a01;
            sof[(2 * 16 + o0) * 4 + px] = a02;
            sof[(3 * 16 + o0) * 4 + px] = a03;
            sof[(0 * 16 + o1) * 4 + px] = a10;
            sof[(1 * 16 + o1) * 4 + px] = a11;
            sof[(2 * 16 + o1) * 4 + px] = a12;
            sof[(3 * 16 + o1) * 4 + px] = a13;
        }
        __syncthreads();   // S4: sout ready; all weight-slot + x reads of chunk j done

        // Weight TMA halves for chunk j+2 into this (now free) slot.
        if (t == 0) {
            const int gn = gi + 2 * GRID;
            if (gn < GROUPS) {
                const float* sp = wts + (size_t)gn * CHUNK_FLOATS;
                const uint32_t d = smem_u32(swt) + slot * CHUNK_BYTES;
                mbar_expect_tx(mb + slot * 16, HALF_BYTES);
                tma_bulk_g2s(d, sp, HALF_BYTES, mb + slot * 16);
                mbar_expect_tx(mb + slot * 16 + 8, HALF_BYTES);
                tma_bulk_g2s(d + HALF_BYTES, sp + CHUNK_FLOATS / 2, HALF_BYTES, mb + slot * 16 + 8);
            }
        }

        // Coalesced write: thread t<64 -> (b = t>>4, o = t&15), float4 over 4 pixels.
        if (t < 64) {
            float4 v = sof4[t];
            v.x += bs0; v.y += bs1; v.z += bs2; v.w += bs3;
            *reinterpret_cast<float4*>(out + (size_t)t * (Hc * Wc) + gi * 4) = v;
            bs0 = bn0; bs1 = bn1; bs2 = bn2; bs3 = bn3;
        }
    }
}

extern "C" void kernel_launch(void* const* d_in, const int* in_sizes, int n_in,
                              void* d_out, int out_size) {
    const float* x    = (const float*)d_in[0];
    const float* wts  = (const float*)d_in[1];
    const float* bias = (const float*)d_in[2];
    float* out        = (float*)d_out;

    cudaFuncSetAttribute(xonv2d_kernel, cudaFuncAttributeMaxDynamicSharedMemorySize, SMEM_TOTAL);
    xonv2d_kernel<<<GRID, NT, SMEM_TOTAL>>>(x, wts, bias, out);
}